// round 3
// baseline (speedup 1.0000x reference)
#include <cuda_runtime.h>
#include <cstdint>

#define BATCH   8
#define NHEADS  16
#define EMB     64
#define SHAPE   64
#define SEQ     4096          // SHAPE*SHAPE
#define NW      127
#define SSTR    1024          // NHEADS*EMB floats between consecutive s rows

// Scratch (8 MB total). Layout for all: [b][h][x][e], e contiguous.
__device__ __align__(128) float g_f [BATCH*NHEADS*SHAPE*EMB];
__device__ __align__(128) float g_u [BATCH*NHEADS*SHAPE*EMB];
__device__ __align__(128) float g_rv[BATCH*NHEADS*SHAPE*EMB];
__device__ __align__(128) float g_ru[BATCH*NHEADS*SHAPE*EMB];

// ---------------------------------------------------------------------------
// Kernel A: stream v, produce f[b,h,s2,e] and u[b,h,s1,e].
// Grid 512 = (b, h, e-quarter). 256 threads = 8 warps.
// Warp w owns s2 in [8w, 8w+8); lane l: jrow = l>>2 (s2 offset), e4g = l&3.
// Per s1: one float4 load per lane (warp = 8 x 64B segments).
// u: 3-step xor-shuffle over jrow, cross-warp via double-buffered smem stage.
// ---------------------------------------------------------------------------
__global__ __launch_bounds__(256)
void kA(const float* __restrict__ v) {
    const int bid = blockIdx.x;
    const int eq  = bid & 3;            // e-quarter (16 floats)
    const int h   = (bid >> 2) & 15;
    const int b   = bid >> 6;

    const int t    = threadIdx.x;
    const int w    = t >> 5;            // warp 0..7
    const int l    = t & 31;
    const int jrow = l >> 2;            // 0..7
    const int e4g  = l & 3;             // 0..3
    const int s2   = w * 8 + jrow;
    const int ebase = eq * 16 + e4g * 4;

    __shared__ float4 red[2][8][8][4];  // [buf][warp][s1 in tile][e4g]

    const float* vb = v + ((size_t)b * SEQ * NHEADS + h) * EMB + ebase
                        + (size_t)s2 * SSTR;
    const size_t bh = (size_t)(b * NHEADS + h) * SHAPE * EMB;

    float4 f4 = make_float4(0.f, 0.f, 0.f, 0.f);

    for (int tile = 0; tile < 8; ++tile) {
        const int s1b = tile * 8;
        float4 p[8];
        #pragma unroll
        for (int i = 0; i < 8; ++i)
            p[i] = *(const float4*)(vb + (size_t)(s1b + i) * 64 * SSTR);

        #pragma unroll
        for (int i = 0; i < 8; ++i) {
            f4.x += p[i].x; f4.y += p[i].y; f4.z += p[i].z; f4.w += p[i].w;
            float4 s = p[i];                       // reduce over jrow
            #pragma unroll
            for (int m = 4; m <= 16; m <<= 1) {
                s.x += __shfl_xor_sync(0xffffffffu, s.x, m);
                s.y += __shfl_xor_sync(0xffffffffu, s.y, m);
                s.z += __shfl_xor_sync(0xffffffffu, s.z, m);
                s.w += __shfl_xor_sync(0xffffffffu, s.w, m);
            }
            if (l < 4) red[tile & 1][w][i][l] = s;
        }
        __syncthreads();
        // reduce previous stage: 32 threads sum 8 warp-partials per (s1, e4g)
        if (t < 32) {
            const int s1t = t >> 2, eg = t & 3;
            float4 a = make_float4(0.f, 0.f, 0.f, 0.f);
            #pragma unroll
            for (int w2 = 0; w2 < 8; ++w2) {
                const float4 r = red[tile & 1][w2][s1t][eg];
                a.x += r.x; a.y += r.y; a.z += r.z; a.w += r.w;
            }
            *(float4*)&g_u[bh + (size_t)(s1b + s1t) * EMB + eq * 16 + eg * 4] = a;
        }
        // next tile writes the other buffer; barrier at tile+1 protects reuse
    }
    *(float4*)&g_f[bh + (size_t)s2 * EMB + ebase] = f4;
}

// ---------------------------------------------------------------------------
// Kernel B: RxV[j] = sum_s K[j,s] f[s],  RxU[j] = sum_s K[j,s] u[s]
// with K[j,s] = w_ext[j + 64 - s], w_ext[127] aliases w[0].
// Grid 1024 = (b, h, j-octet). 128 threads: e4 = t&15, j = 8*jo + (t>>4).
// Packed f32x2 FMAs (PTX-only; halves FFMA count).
// ---------------------------------------------------------------------------
__global__ __launch_bounds__(128)
void kB(const float* __restrict__ wg) {
    const int bid = blockIdx.x;
    const int jo  = bid & 7;
    const int h   = (bid >> 3) & 15;
    const int b   = bid >> 7;
    const int t   = threadIdx.x;

    __shared__ float  wext[128];
    __shared__ float4 fs[1024];   // [s][e4]
    __shared__ float4 us[1024];

    wext[t] = wg[h * NW + ((t < NW) ? t : 0)];   // wext[127] = w[0]

    const size_t bh = (size_t)(b * NHEADS + h) * SHAPE * EMB;
    const float4* gf4 = (const float4*)&g_f[bh];
    const float4* gu4 = (const float4*)&g_u[bh];
    #pragma unroll
    for (int k = 0; k < 8; ++k) {
        fs[t + k * 128] = gf4[t + k * 128];
        us[t + k * 128] = gu4[t + k * 128];
    }
    __syncthreads();

    const int e4 = t & 15;
    const int j  = jo * 8 + (t >> 4);

    unsigned long long rv0 = 0, rv1 = 0, ru0 = 0, ru1 = 0;
    #pragma unroll 4
    for (int s = 0; s < 64; ++s) {
        const float wsc = wext[j + 64 - s];
        unsigned long long w2;
        asm("mov.b64 %0, {%1, %1};" : "=l"(w2) : "r"(__float_as_uint(wsc)));
        const ulonglong2 fv = *(const ulonglong2*)&fs[s * 16 + e4];
        const ulonglong2 uv = *(const ulonglong2*)&us[s * 16 + e4];
        asm("fma.rn.f32x2 %0, %1, %2, %0;" : "+l"(rv0) : "l"(fv.x), "l"(w2));
        asm("fma.rn.f32x2 %0, %1, %2, %0;" : "+l"(rv1) : "l"(fv.y), "l"(w2));
        asm("fma.rn.f32x2 %0, %1, %2, %0;" : "+l"(ru0) : "l"(uv.x), "l"(w2));
        asm("fma.rn.f32x2 %0, %1, %2, %0;" : "+l"(ru1) : "l"(uv.y), "l"(w2));
    }
    ulonglong2 o1; o1.x = rv0; o1.y = rv1;
    ulonglong2 o2; o2.x = ru0; o2.y = ru1;
    *(ulonglong2*)&g_rv[bh + (size_t)j * EMB + e4 * 4] = o1;
    *(ulonglong2*)&g_ru[bh + (size_t)j * EMB + e4 * 4] = o2;
}

// ---------------------------------------------------------------------------
// Kernel C: out[b, s1*64+s2, h, e] = RxV[b,h,s2,e] + RxU[b,h,s1,e]
// Grid 1024 = (b, h, s1-octet). 256 threads: e4 = t&15, sg = t>>4 (s2 = sg+16k).
// rv/ru come from L2 (4 MB resident); 128 MB of float4 stores.
// ---------------------------------------------------------------------------
__global__ __launch_bounds__(256)
void kC(float* __restrict__ out) {
    const int bid = blockIdx.x;
    const int so  = bid & 7;            // s1 octet
    const int h   = (bid >> 3) & 15;
    const int b   = bid >> 7;
    const int t   = threadIdx.x;
    const int e4  = t & 15;
    const int sg  = t >> 4;             // 0..15

    const size_t bh = (size_t)(b * NHEADS + h) * SHAPE * EMB;

    float4 rv[4];
    #pragma unroll
    for (int k = 0; k < 4; ++k)
        rv[k] = *(const float4*)&g_rv[bh + (size_t)(sg + 16 * k) * EMB + e4 * 4];

    float* ob = out + ((size_t)b * SEQ * NHEADS + h) * EMB + e4 * 4;
    #pragma unroll
    for (int i = 0; i < 8; ++i) {
        const int s1 = so * 8 + i;
        const float4 ru = *(const float4*)&g_ru[bh + (size_t)s1 * EMB + e4 * 4];
        #pragma unroll
        for (int k = 0; k < 4; ++k) {
            const int s2 = sg + 16 * k;
            float4 o;
            o.x = rv[k].x + ru.x;
            o.y = rv[k].y + ru.y;
            o.z = rv[k].z + ru.z;
            o.w = rv[k].w + ru.w;
            *(float4*)(ob + (size_t)(s1 * 64 + s2) * SSTR) = o;
        }
    }
}

extern "C" void kernel_launch(void* const* d_in, const int* in_sizes, int n_in,
                              void* d_out, int out_size) {
    (void)in_sizes; (void)n_in; (void)out_size;
    const float* v = (const float*)d_in[0];   // [8, 4096, 16, 64] f32
    const float* w = (const float*)d_in[1];   // [1, 16, 127]      f32
    float* o = (float*)d_out;                 // [8, 4096, 16, 64] f32

    kA<<<512,  256>>>(v);
    kB<<<1024, 128>>>(w);
    kC<<<1024, 256>>>(o);
}